// round 3
// baseline (speedup 1.0000x reference)
#include <cuda_runtime.h>
#include <cstdint>
#include <cstddef>

#define N_JOBS 100000
#define N_MACH 10000
#define DIM 128
#define KDIM 256
#define BM 64
#define THREADS 512
#define XSTR 264            // padded Xs row stride (floats)
#define MAX_EDGES 1600000
#define LN_EPS 1e-5f

// CSR scratch (~14 MB of device globals; no allocations allowed).
__device__ int g_job_off[N_JOBS + 1];
__device__ int g_mach_off[N_MACH + 1];
__device__ int g_job_cur[N_JOBS];
__device__ int g_mach_cur[N_MACH];
__device__ int g_job_nbr[MAX_EDGES];   // machine index per edge, grouped by job
__device__ int g_mach_nbr[MAX_EDGES];  // job index per edge, grouped by machine

__global__ void zero_cnt_kernel() {
    int i = blockIdx.x * blockDim.x + threadIdx.x;
    int stride = gridDim.x * blockDim.x;
    for (int t = i; t < N_JOBS; t += stride) g_job_cur[t] = 0;
    for (int t = i; t < N_MACH; t += stride) g_mach_cur[t] = 0;
}

__global__ void hist_kernel(const int* __restrict__ job_idx,
                            const int* __restrict__ mach_idx, int n_edges) {
    int i = blockIdx.x * blockDim.x + threadIdx.x;
    int stride = gridDim.x * blockDim.x;
    for (int e = i; e < n_edges; e += stride) {
        atomicAdd(&g_job_cur[job_idx[e]], 1);
        atomicAdd(&g_mach_cur[mach_idx[e]], 1);
    }
}

// Single-block exclusive scan per array. Block 0: jobs, block 1: machines.
// Writes off[] (exclusive, off[n] = total) and resets cur[] = off[] as fill cursors.
__global__ void scan_kernel() {
    int* cnt = blockIdx.x ? g_mach_cur : g_job_cur;
    int* off = blockIdx.x ? g_mach_off : g_job_off;
    int n    = blockIdx.x ? N_MACH : N_JOBS;

    __shared__ int warp_sums[16];
    __shared__ int s_running;
    int tid = threadIdx.x;
    int lane = tid & 31, wid = tid >> 5;
    if (tid == 0) s_running = 0;
    __syncthreads();

    for (int base = 0; base < n; base += THREADS * 4) {
        int idx = base + tid * 4;
        int v[4];
        #pragma unroll
        for (int k = 0; k < 4; k++) v[k] = (idx + k < n) ? cnt[idx + k] : 0;
        int tsum = v[0] + v[1] + v[2] + v[3];
        // warp inclusive scan of tsum
        int incl = tsum;
        #pragma unroll
        for (int o = 1; o < 32; o <<= 1) {
            int t = __shfl_up_sync(0xffffffffu, incl, o);
            if (lane >= o) incl += t;
        }
        if (lane == 31) warp_sums[wid] = incl;
        __syncthreads();
        if (wid == 0 && lane < 16) {
            int ws = warp_sums[lane];
            #pragma unroll
            for (int o = 1; o < 16; o <<= 1) {
                int t = __shfl_up_sync(0xffffu, ws, o);
                if (lane >= o) ws += t;
            }
            warp_sums[lane] = ws;
        }
        __syncthreads();
        int running = s_running;
        int warp_excl = (wid == 0) ? 0 : warp_sums[wid - 1];
        int run = running + warp_excl + (incl - tsum);
        #pragma unroll
        for (int k = 0; k < 4; k++) {
            if (idx + k < n) { off[idx + k] = run; cnt[idx + k] = run; }
            run += v[k];
        }
        __syncthreads();
        if (tid == 0) s_running += warp_sums[15];
        __syncthreads();
    }
    if (tid == 0) off[n] = s_running;
}

__global__ void fill_kernel(const int* __restrict__ job_idx,
                            const int* __restrict__ mach_idx, int n_edges) {
    int i = blockIdx.x * blockDim.x + threadIdx.x;
    int stride = gridDim.x * blockDim.x;
    for (int e = i; e < n_edges; e += stride) {
        int j = job_idx[e];
        int m = mach_idx[e];
        int pj = atomicAdd(&g_job_cur[j], 1);
        g_job_nbr[pj] = m;
        int pm = atomicAdd(&g_mach_cur[m], 1);
        g_mach_nbr[pm] = j;
    }
}

// Fused per 64-row tile: gather neighbor-mean (CSR) + own features into Xs,
// then Y = relu([h | agg] @ W^T + b), out = LayerNorm(Y).
// 512 threads. Gather: thread (r=tid>>3, sub=tid&7) owns 64B of the row.
// GEMM: warp tr=tid>>5 owns rows tr*4..tr*4+3; lane tc owns cols tc*4..tc*4+3.
// Wt swizzled so b-loads are conflict-free LDS.128; a-loads are warp-broadcast.
// Inner product uses packed fma.rn.f32x2. LN via warp shfl reduction.
__global__ __launch_bounds__(THREADS, 1) void fused_kernel(
    const float* __restrict__ h,       // own features [n_rows][128]
    const float* __restrict__ gtab,    // gather table (other side) [*][128]
    const float* __restrict__ W,       // [128][256]
    const float* __restrict__ bias,
    const float* __restrict__ ln_s,
    const float* __restrict__ ln_b,
    float* __restrict__ out,
    int n_rows, int mode)
{
    const int* off = mode ? g_mach_off : g_job_off;
    const int* nbr = mode ? g_mach_nbr : g_job_nbr;
    extern __shared__ float smem[];
    float* Wt = smem;                    // 256 x 128, swizzled transpose
    float* Xs = smem + KDIM * DIM;       // 64 x XSTR
    int tid = threadIdx.x;
    int row0 = blockIdx.x * BM;

    // W -> shared, transposed + swizzled: (k,o) at k*128 + (o ^ ((k>>2&7)<<2))
    #pragma unroll
    for (int it = 0; it < 16; it++) {
        int idx4 = tid + it * THREADS;       // 8192 float4 of W
        int o = idx4 >> 6;
        int kb = (idx4 & 63) << 2;
        float4 w = *(const float4*)(W + o * KDIM + kb);
        int oo = o ^ (((kb >> 2) & 7) << 2);
        Wt[(kb + 0) * DIM + oo] = w.x;
        Wt[(kb + 1) * DIM + oo] = w.y;
        Wt[(kb + 2) * DIM + oo] = w.z;
        Wt[(kb + 3) * DIM + oo] = w.w;
    }

    // Gather + own-feature load. 8 threads per row; each owns 4 float4 (64B).
    {
        int r = tid >> 3;
        int sub = tid & 7;
        int grow = row0 + r;
        int cb = sub * 16;
        float4 a0 = make_float4(0.f,0.f,0.f,0.f), a1 = a0, a2 = a0, a3 = a0;
        float4 h0 = a0, h1 = a0, h2 = a0, h3 = a0;
        if (grow < n_rows) {
            const float4* hp = (const float4*)(h + (size_t)grow * DIM + cb);
            h0 = hp[0]; h1 = hp[1]; h2 = hp[2]; h3 = hp[3];
            int s = off[grow], e = off[grow + 1];
            for (int p = s; p < e; p++) {
                int nb = nbr[p];
                const float4* rp = (const float4*)(gtab + (size_t)nb * DIM + cb);
                float4 b0 = rp[0], b1 = rp[1], b2 = rp[2], b3 = rp[3];
                a0.x += b0.x; a0.y += b0.y; a0.z += b0.z; a0.w += b0.w;
                a1.x += b1.x; a1.y += b1.y; a1.z += b1.z; a1.w += b1.w;
                a2.x += b2.x; a2.y += b2.y; a2.z += b2.z; a2.w += b2.w;
                a3.x += b3.x; a3.y += b3.y; a3.z += b3.z; a3.w += b3.w;
            }
            float idg = 1.0f / (float)max(e - s, 1);
            a0.x*=idg; a0.y*=idg; a0.z*=idg; a0.w*=idg;
            a1.x*=idg; a1.y*=idg; a1.z*=idg; a1.w*=idg;
            a2.x*=idg; a2.y*=idg; a2.z*=idg; a2.w*=idg;
            a3.x*=idg; a3.y*=idg; a3.z*=idg; a3.w*=idg;
        }
        float* xr = Xs + (size_t)r * XSTR;
        *(float4*)(xr + cb + 0)  = h0;
        *(float4*)(xr + cb + 4)  = h1;
        *(float4*)(xr + cb + 8)  = h2;
        *(float4*)(xr + cb + 12) = h3;
        *(float4*)(xr + DIM + cb + 0)  = a0;
        *(float4*)(xr + DIM + cb + 4)  = a1;
        *(float4*)(xr + DIM + cb + 8)  = a2;
        *(float4*)(xr + DIM + cb + 12) = a3;
    }
    __syncthreads();

    int tc = tid & 31;
    int tr = tid >> 5;
    unsigned long long acc[4][2];
    #pragma unroll
    for (int i = 0; i < 4; i++) { acc[i][0] = 0ull; acc[i][1] = 0ull; }

    const float* xrow = Xs + (size_t)(tr * 4) * XSTR;

    #pragma unroll 2
    for (int k0 = 0; k0 < KDIM; k0 += 4) {
        int s = (k0 >> 2) & 7;
        const float* wp = Wt + (size_t)k0 * DIM + ((tc ^ s) << 2);
        ulonglong2 bq[4];
        #pragma unroll
        for (int kk = 0; kk < 4; kk++)
            bq[kk] = *(const ulonglong2*)(wp + kk * DIM);
        #pragma unroll
        for (int i = 0; i < 4; i++) {
            float4 a = *(const float4*)(xrow + i * XSTR + k0);
            float av[4] = {a.x, a.y, a.z, a.w};
            #pragma unroll
            for (int kk = 0; kk < 4; kk++) {
                unsigned long long aa;
                asm("mov.b64 %0, {%1, %1};" : "=l"(aa) : "f"(av[kk]));
                asm("fma.rn.f32x2 %0, %1, %2, %0;" : "+l"(acc[i][0]) : "l"(aa), "l"(bq[kk].x));
                asm("fma.rn.f32x2 %0, %1, %2, %0;" : "+l"(acc[i][1]) : "l"(aa), "l"(bq[kk].y));
            }
        }
    }

    // Epilogue: +bias, relu, LayerNorm per row (row spread over one warp), store.
    float4 bb = *(const float4*)(bias + tc * 4);
    float4 gs = *(const float4*)(ln_s + tc * 4);
    float4 gb = *(const float4*)(ln_b + tc * 4);

    #pragma unroll
    for (int i = 0; i < 4; i++) {
        int grow = row0 + tr * 4 + i;
        float v0, v1, v2, v3;
        asm("mov.b64 {%0, %1}, %2;" : "=f"(v0), "=f"(v1) : "l"(acc[i][0]));
        asm("mov.b64 {%0, %1}, %2;" : "=f"(v2), "=f"(v3) : "l"(acc[i][1]));
        v0 = fmaxf(v0 + bb.x, 0.f);
        v1 = fmaxf(v1 + bb.y, 0.f);
        v2 = fmaxf(v2 + bb.z, 0.f);
        v3 = fmaxf(v3 + bb.w, 0.f);
        float sum = v0 + v1 + v2 + v3;
        float sq  = v0*v0 + v1*v1 + v2*v2 + v3*v3;
        #pragma unroll
        for (int o = 16; o > 0; o >>= 1) {
            sum += __shfl_xor_sync(0xffffffffu, sum, o);
            sq  += __shfl_xor_sync(0xffffffffu, sq,  o);
        }
        float mean = sum * (1.0f / 128.0f);
        float var  = sq * (1.0f / 128.0f) - mean * mean;
        float rstd = rsqrtf(var + LN_EPS);
        if (grow < n_rows) {
            float4 o4;
            o4.x = (v0 - mean) * rstd * gs.x + gb.x;
            o4.y = (v1 - mean) * rstd * gs.y + gb.y;
            o4.z = (v2 - mean) * rstd * gs.z + gb.z;
            o4.w = (v3 - mean) * rstd * gs.w + gb.w;
            *(float4*)(out + (size_t)grow * DIM + tc * 4) = o4;
        }
    }
}

extern "C" void kernel_launch(void* const* d_in, const int* in_sizes, int n_in,
                              void* d_out, int out_size)
{
    const float* job_h     = (const float*)d_in[0];
    const float* machine_h = (const float*)d_in[1];
    const float* W_job_w   = (const float*)d_in[2];
    const float* W_job_b   = (const float*)d_in[3];
    const float* W_mach_w  = (const float*)d_in[4];
    const float* W_mach_b  = (const float*)d_in[5];
    const float* lnj_s     = (const float*)d_in[6];
    const float* lnj_b     = (const float*)d_in[7];
    const float* lnm_s     = (const float*)d_in[8];
    const float* lnm_b     = (const float*)d_in[9];
    const int*   job_idx   = (const int*)d_in[10];
    const int*   mach_idx  = (const int*)d_in[11];
    float* out = (float*)d_out;
    int n_edges = in_sizes[10];

    const int smem_bytes = (KDIM * DIM + BM * XSTR) * (int)sizeof(float);  // 198656
    cudaFuncSetAttribute(fused_kernel, cudaFuncAttributeMaxDynamicSharedMemorySize, smem_bytes);

    zero_cnt_kernel<<<128, 256>>>();
    hist_kernel<<<1024, 256>>>(job_idx, mach_idx, n_edges);
    scan_kernel<<<2, THREADS>>>();
    fill_kernel<<<1024, 256>>>(job_idx, mach_idx, n_edges);

    fused_kernel<<<(N_JOBS + BM - 1) / BM, THREADS, smem_bytes>>>(
        job_h, machine_h, W_job_w, W_job_b, lnj_s, lnj_b, out, N_JOBS, 0);
    fused_kernel<<<(N_MACH + BM - 1) / BM, THREADS, smem_bytes>>>(
        machine_h, job_h, W_mach_w, W_mach_b, lnm_s, lnm_b,
        out + (size_t)N_JOBS * DIM, N_MACH, 1);
}

// round 5
// speedup vs baseline: 1.1263x; 1.1263x over previous
#include <cuda_runtime.h>
#include <cstdint>
#include <cstddef>

#define N_JOBS 100000
#define N_MACH 10000
#define DIM 128
#define KDIM 256
#define BM 64
#define THREADS 512
#define XSTR 264            // padded Xs row stride (floats)
#define MAX_EDGES 1600000
#define LN_EPS 1e-5f

#define SCAN_CHUNK 512
#define JB ((N_JOBS + SCAN_CHUNK - 1) / SCAN_CHUNK)   // 196
#define MB ((N_MACH + SCAN_CHUNK - 1) / SCAN_CHUNK)   // 20

// CSR scratch (~14 MB of device globals; no allocations allowed).
__device__ int g_job_off[N_JOBS + 1];
__device__ int g_mach_off[N_MACH + 1];
__device__ int g_job_cur[N_JOBS];
__device__ int g_mach_cur[N_MACH];
__device__ int g_job_nbr[MAX_EDGES];   // machine index per edge, grouped by job
__device__ int g_mach_nbr[MAX_EDGES];  // job index per edge, grouped by machine
__device__ int g_bsum[JB + MB];

__global__ void zero_cnt_kernel() {
    int i = blockIdx.x * blockDim.x + threadIdx.x;
    int stride = gridDim.x * blockDim.x;
    for (int t = i; t < N_JOBS; t += stride) g_job_cur[t] = 0;
    for (int t = i; t < N_MACH; t += stride) g_mach_cur[t] = 0;
}

__global__ void hist_kernel(const int* __restrict__ job_idx,
                            const int* __restrict__ mach_idx, int n_edges) {
    int i = blockIdx.x * blockDim.x + threadIdx.x;
    int stride = gridDim.x * blockDim.x;
    for (int e = i; e < n_edges; e += stride) {
        atomicAdd(&g_job_cur[__ldg(job_idx + e)], 1);
        atomicAdd(&g_mach_cur[__ldg(mach_idx + e)], 1);
    }
}

// Pass A: per-block (512 elems) local exclusive scan into off[], block total -> g_bsum.
__global__ void scanA_kernel() {
    bool is_mach = blockIdx.x >= JB;
    const int* cnt = is_mach ? g_mach_cur : g_job_cur;
    int* off = is_mach ? g_mach_off : g_job_off;
    int n    = is_mach ? N_MACH : N_JOBS;
    int b    = is_mach ? (blockIdx.x - JB) : blockIdx.x;

    int tid = threadIdx.x;            // 256 threads, 2 elems each
    int lane = tid & 31, wid = tid >> 5;
    int idx = b * SCAN_CHUNK + tid * 2;
    int v0 = (idx     < n) ? cnt[idx]     : 0;
    int v1 = (idx + 1 < n) ? cnt[idx + 1] : 0;
    int tsum = v0 + v1;
    int incl = tsum;
    #pragma unroll
    for (int o = 1; o < 32; o <<= 1) {
        int t = __shfl_up_sync(0xffffffffu, incl, o);
        if (lane >= o) incl += t;
    }
    __shared__ int wsum[8];
    if (lane == 31) wsum[wid] = incl;
    __syncthreads();
    if (tid < 8) {
        int ws = wsum[tid];
        #pragma unroll
        for (int o = 1; o < 8; o <<= 1) {
            int t = __shfl_up_sync(0xffu, ws, o);
            if (tid >= o) ws += t;
        }
        wsum[tid] = ws;
    }
    __syncthreads();
    int base = (wid == 0 ? 0 : wsum[wid - 1]) + (incl - tsum);
    if (idx     < n) off[idx]     = base;
    if (idx + 1 < n) off[idx + 1] = base + v0;
    if (tid == 255) g_bsum[blockIdx.x] = wsum[7];
}

// Pass B: one block exclusive-scans g_bsum for jobs [0,JB) and machines [JB,JB+MB).
__global__ void scanB_kernel(int n_edges) {
    int tid = threadIdx.x;   // 256 >= max(JB, MB)
    int lane = tid & 31, wid = tid >> 5;
    __shared__ int wsum[8];
    #pragma unroll
    for (int seg = 0; seg < 2; seg++) {
        int n = seg ? MB : JB;
        int o0 = seg ? JB : 0;
        int v = (tid < n) ? g_bsum[o0 + tid] : 0;
        int incl = v;
        #pragma unroll
        for (int o = 1; o < 32; o <<= 1) {
            int t = __shfl_up_sync(0xffffffffu, incl, o);
            if (lane >= o) incl += t;
        }
        if (lane == 31) wsum[wid] = incl;
        __syncthreads();
        if (tid < 8) {
            int ws = wsum[tid];
            #pragma unroll
            for (int o = 1; o < 8; o <<= 1) {
                int t = __shfl_up_sync(0xffu, ws, o);
                if (tid >= o) ws += t;
            }
            wsum[tid] = ws;
        }
        __syncthreads();
        int excl = (wid == 0 ? 0 : wsum[wid - 1]) + (incl - v);
        if (tid < n) g_bsum[o0 + tid] = excl;
        __syncthreads();
    }
    if (tid == 0) { g_job_off[N_JOBS] = n_edges; g_mach_off[N_MACH] = n_edges; }
}

// Pass C: add block bases, copy off -> cur (fill cursors).
__global__ void scanC_kernel() {
    bool is_mach = blockIdx.x >= JB;
    int* off = is_mach ? g_mach_off : g_job_off;
    int* cur = is_mach ? g_mach_cur : g_job_cur;
    int n    = is_mach ? N_MACH : N_JOBS;
    int b    = is_mach ? (blockIdx.x - JB) : blockIdx.x;
    int base = g_bsum[blockIdx.x];
    int idx = b * SCAN_CHUNK + threadIdx.x * 2;
    if (idx < n)     { int v = off[idx]     + base; off[idx]     = v; cur[idx]     = v; }
    if (idx + 1 < n) { int v = off[idx + 1] + base; off[idx + 1] = v; cur[idx + 1] = v; }
}

__global__ void fill_kernel(const int* __restrict__ job_idx,
                            const int* __restrict__ mach_idx, int n_edges) {
    int i = blockIdx.x * blockDim.x + threadIdx.x;
    int stride = gridDim.x * blockDim.x;
    for (int e = i; e < n_edges; e += stride) {
        int j = __ldg(job_idx + e);
        int m = __ldg(mach_idx + e);
        int pj = atomicAdd(&g_job_cur[j], 1);
        g_job_nbr[pj] = m;
        int pm = atomicAdd(&g_mach_cur[m], 1);
        g_mach_nbr[pm] = j;
    }
}

// Fused per 64-row tile: gather neighbor-mean (CSR) + own features into Xs,
// then Y = relu([h | agg] @ W^T + b), out = LayerNorm(Y).
// 512 threads. Gather: thread (r=tid>>3, sub=tid&7) owns 64B of the row.
// GEMM: warp tr=tid>>5 owns rows tr*4..tr*4+3; lane tc owns cols tc*4..tc*4+3.
// Wt swizzled so b-loads are conflict-free LDS.128; a-loads are warp-broadcast.
// Bounded unrolls keep regs < 128 (no spills at 512 threads).
__global__ __launch_bounds__(THREADS, 1) void fused_kernel(
    const float* __restrict__ h,       // own features [n_rows][128]
    const float* __restrict__ gtab,    // gather table (other side) [*][128]
    const float* __restrict__ W,       // [128][256]
    const float* __restrict__ bias,
    const float* __restrict__ ln_s,
    const float* __restrict__ ln_b,
    float* __restrict__ out,
    int n_rows, int mode)
{
    const int* off = mode ? g_mach_off : g_job_off;
    const int* nbr = mode ? g_mach_nbr : g_job_nbr;
    extern __shared__ float smem[];
    float* Wt = smem;                    // 256 x 128, swizzled transpose
    float* Xs = smem + KDIM * DIM;       // 64 x XSTR
    int tid = threadIdx.x;
    int row0 = blockIdx.x * BM;

    // W -> shared, transposed + swizzled: (k,o) at k*128 + (o ^ ((k>>2&7)<<2)).
    // Bounded unroll: few float4 live at a time.
    #pragma unroll 4
    for (int it = 0; it < 16; it++) {
        int idx4 = tid + it * THREADS;       // 8192 float4 of W
        int o = idx4 >> 6;
        int kb = (idx4 & 63) << 2;
        float4 w = *(const float4*)(W + o * KDIM + kb);
        int oo = o ^ (((kb >> 2) & 7) << 2);
        Wt[(kb + 0) * DIM + oo] = w.x;
        Wt[(kb + 1) * DIM + oo] = w.y;
        Wt[(kb + 2) * DIM + oo] = w.z;
        Wt[(kb + 3) * DIM + oo] = w.w;
    }

    // Gather + own-feature load. 8 threads per row; each owns 4 float4 (64B).
    {
        int r = tid >> 3;
        int sub = tid & 7;
        int grow = row0 + r;
        int cb = sub * 16;
        float4 a0 = make_float4(0.f,0.f,0.f,0.f), a1 = a0, a2 = a0, a3 = a0;
        float* xr = Xs + (size_t)r * XSTR;
        if (grow < n_rows) {
            const float4* hp = (const float4*)(h + (size_t)grow * DIM + cb);
            float4 h0 = hp[0], h1 = hp[1], h2 = hp[2], h3 = hp[3];
            *(float4*)(xr + cb + 0)  = h0;
            *(float4*)(xr + cb + 4)  = h1;
            *(float4*)(xr + cb + 8)  = h2;
            *(float4*)(xr + cb + 12) = h3;
            int s = off[grow], e = off[grow + 1];
            int p = s;
            // unroll-by-2: 8 independent float4 loads in flight
            for (; p + 2 <= e; p += 2) {
                int nb0 = __ldg(nbr + p);
                int nb1 = __ldg(nbr + p + 1);
                const float4* rp0 = (const float4*)(gtab + (size_t)nb0 * DIM + cb);
                const float4* rp1 = (const float4*)(gtab + (size_t)nb1 * DIM + cb);
                float4 b0 = rp0[0], b1 = rp0[1], b2 = rp0[2], b3 = rp0[3];
                float4 c0 = rp1[0], c1 = rp1[1], c2 = rp1[2], c3 = rp1[3];
                a0.x += b0.x + c0.x; a0.y += b0.y + c0.y; a0.z += b0.z + c0.z; a0.w += b0.w + c0.w;
                a1.x += b1.x + c1.x; a1.y += b1.y + c1.y; a1.z += b1.z + c1.z; a1.w += b1.w + c1.w;
                a2.x += b2.x + c2.x; a2.y += b2.y + c2.y; a2.z += b2.z + c2.z; a2.w += b2.w + c2.w;
                a3.x += b3.x + c3.x; a3.y += b3.y + c3.y; a3.z += b3.z + c3.z; a3.w += b3.w + c3.w;
            }
            if (p < e) {
                int nb0 = __ldg(nbr + p);
                const float4* rp0 = (const float4*)(gtab + (size_t)nb0 * DIM + cb);
                float4 b0 = rp0[0], b1 = rp0[1], b2 = rp0[2], b3 = rp0[3];
                a0.x += b0.x; a0.y += b0.y; a0.z += b0.z; a0.w += b0.w;
                a1.x += b1.x; a1.y += b1.y; a1.z += b1.z; a1.w += b1.w;
                a2.x += b2.x; a2.y += b2.y; a2.z += b2.z; a2.w += b2.w;
                a3.x += b3.x; a3.y += b3.y; a3.z += b3.z; a3.w += b3.w;
            }
            float idg = 1.0f / (float)max(e - s, 1);
            a0.x*=idg; a0.y*=idg; a0.z*=idg; a0.w*=idg;
            a1.x*=idg; a1.y*=idg; a1.z*=idg; a1.w*=idg;
            a2.x*=idg; a2.y*=idg; a2.z*=idg; a2.w*=idg;
            a3.x*=idg; a3.y*=idg; a3.z*=idg; a3.w*=idg;
        } else {
            *(float4*)(xr + cb + 0)  = a0;
            *(float4*)(xr + cb + 4)  = a0;
            *(float4*)(xr + cb + 8)  = a0;
            *(float4*)(xr + cb + 12) = a0;
        }
        *(float4*)(xr + DIM + cb + 0)  = a0;
        *(float4*)(xr + DIM + cb + 4)  = a1;
        *(float4*)(xr + DIM + cb + 8)  = a2;
        *(float4*)(xr + DIM + cb + 12) = a3;
    }
    __syncthreads();

    int tc = tid & 31;
    int tr = tid >> 5;
    unsigned long long acc[4][2];
    #pragma unroll
    for (int i = 0; i < 4; i++) { acc[i][0] = 0ull; acc[i][1] = 0ull; }

    const float* xrow = Xs + (size_t)(tr * 4) * XSTR;

    #pragma unroll 2
    for (int k0 = 0; k0 < KDIM; k0 += 4) {
        int s = (k0 >> 2) & 7;
        const float* wp = Wt + (size_t)k0 * DIM + ((tc ^ s) << 2);
        ulonglong2 bq[4];
        #pragma unroll
        for (int kk = 0; kk < 4; kk++)
            bq[kk] = *(const ulonglong2*)(wp + kk * DIM);
        #pragma unroll
        for (int i = 0; i < 4; i++) {
            float4 a = *(const float4*)(xrow + i * XSTR + k0);
            float av[4] = {a.x, a.y, a.z, a.w};
            #pragma unroll
            for (int kk = 0; kk < 4; kk++) {
                unsigned long long aa;
                asm("mov.b64 %0, {%1, %1};" : "=l"(aa) : "f"(av[kk]));
                asm("fma.rn.f32x2 %0, %1, %2, %0;" : "+l"(acc[i][0]) : "l"(aa), "l"(bq[kk].x));
                asm("fma.rn.f32x2 %0, %1, %2, %0;" : "+l"(acc[i][1]) : "l"(aa), "l"(bq[kk].y));
            }
        }
    }

    // Epilogue: +bias, relu, LayerNorm per row (row spread over one warp), store.
    float4 bb = *(const float4*)(bias + tc * 4);
    float4 gs = *(const float4*)(ln_s + tc * 4);
    float4 gb = *(const float4*)(ln_b + tc * 4);

    #pragma unroll
    for (int i = 0; i < 4; i++) {
        int grow = row0 + tr * 4 + i;
        float v0, v1, v2, v3;
        asm("mov.b64 {%0, %1}, %2;" : "=f"(v0), "=f"(v1) : "l"(acc[i][0]));
        asm("mov.b64 {%0, %1}, %2;" : "=f"(v2), "=f"(v3) : "l"(acc[i][1]));
        v0 = fmaxf(v0 + bb.x, 0.f);
        v1 = fmaxf(v1 + bb.y, 0.f);
        v2 = fmaxf(v2 + bb.z, 0.f);
        v3 = fmaxf(v3 + bb.w, 0.f);
        float sum = v0 + v1 + v2 + v3;
        float sq  = v0*v0 + v1*v1 + v2*v2 + v3*v3;
        #pragma unroll
        for (int o = 16; o > 0; o >>= 1) {
            sum += __shfl_xor_sync(0xffffffffu, sum, o);
            sq  += __shfl_xor_sync(0xffffffffu, sq,  o);
        }
        float mean = sum * (1.0f / 128.0f);
        float var  = sq * (1.0f / 128.0f) - mean * mean;
        float rstd = rsqrtf(var + LN_EPS);
        if (grow < n_rows) {
            float4 o4;
            o4.x = (v0 - mean) * rstd * gs.x + gb.x;
            o4.y = (v1 - mean) * rstd * gs.y + gb.y;
            o4.z = (v2 - mean) * rstd * gs.z + gb.z;
            o4.w = (v3 - mean) * rstd * gs.w + gb.w;
            *(float4*)(out + (size_t)grow * DIM + tc * 4) = o4;
        }
    }
}

extern "C" void kernel_launch(void* const* d_in, const int* in_sizes, int n_in,
                              void* d_out, int out_size)
{
    const float* job_h     = (const float*)d_in[0];
    const float* machine_h = (const float*)d_in[1];
    const float* W_job_w   = (const float*)d_in[2];
    const float* W_job_b   = (const float*)d_in[3];
    const float* W_mach_w  = (const float*)d_in[4];
    const float* W_mach_b  = (const float*)d_in[5];
    const float* lnj_s     = (const float*)d_in[6];
    const float* lnj_b     = (const float*)d_in[7];
    const float* lnm_s     = (const float*)d_in[8];
    const float* lnm_b     = (const float*)d_in[9];
    const int*   job_idx   = (const int*)d_in[10];
    const int*   mach_idx  = (const int*)d_in[11];
    float* out = (float*)d_out;
    int n_edges = in_sizes[10];

    const int smem_bytes = (KDIM * DIM + BM * XSTR) * (int)sizeof(float);  // 198656
    cudaFuncSetAttribute(fused_kernel, cudaFuncAttributeMaxDynamicSharedMemorySize, smem_bytes);

    zero_cnt_kernel<<<128, 256>>>();
    hist_kernel<<<1024, 256>>>(job_idx, mach_idx, n_edges);
    scanA_kernel<<<JB + MB, 256>>>();
    scanB_kernel<<<1, 256>>>(n_edges);
    scanC_kernel<<<JB + MB, 256>>>();
    fill_kernel<<<1024, 256>>>(job_idx, mach_idx, n_edges);

    fused_kernel<<<(N_JOBS + BM - 1) / BM, THREADS, smem_bytes>>>(
        job_h, machine_h, W_job_w, W_job_b, lnj_s, lnj_b, out, N_JOBS, 0);
    fused_kernel<<<(N_MACH + BM - 1) / BM, THREADS, smem_bytes>>>(
        machine_h, job_h, W_mach_w, W_mach_b, lnm_s, lnm_b,
        out + (size_t)N_JOBS * DIM, N_MACH, 1);
}

// round 6
// speedup vs baseline: 1.4947x; 1.3271x over previous
#include <cuda_runtime.h>
#include <cstdint>
#include <cstddef>

#define N_JOBS 100000
#define N_MACH 10000
#define DIM 128
#define KDIM 256
#define BM 64
#define LN_EPS 1e-5f
#define MAX_EDGES 1600000

#define SCAN_CHUNK 512
#define JB ((N_JOBS + SCAN_CHUNK - 1) / SCAN_CHUNK)   // 196
#define MB ((N_MACH + SCAN_CHUNK - 1) / SCAN_CHUNK)   // 20

// Scratch device globals (no allocations allowed): CSR (~14MB) + agg (~56MB).
__device__ int g_job_off[N_JOBS + 1];
__device__ int g_mach_off[N_MACH + 1];
__device__ int g_job_cur[N_JOBS];
__device__ int g_mach_cur[N_MACH];
__device__ int g_job_nbr[MAX_EDGES];
__device__ int g_mach_nbr[MAX_EDGES];
__device__ int g_bsum[JB + MB];
__device__ __align__(256) float g_job_agg[(size_t)N_JOBS * DIM];
__device__ __align__(256) float g_mach_agg[(size_t)N_MACH * DIM];

__global__ void zero_cnt_kernel() {
    int i = blockIdx.x * blockDim.x + threadIdx.x;
    int stride = gridDim.x * blockDim.x;
    for (int t = i; t < N_JOBS; t += stride) g_job_cur[t] = 0;
    for (int t = i; t < N_MACH; t += stride) g_mach_cur[t] = 0;
}

// 4 edges per iteration -> 8 independent atomics in flight (latency-bound kernel).
__global__ void hist_kernel(const int* __restrict__ job_idx,
                            const int* __restrict__ mach_idx, int n_edges) {
    int i = blockIdx.x * blockDim.x + threadIdx.x;
    int stride = gridDim.x * blockDim.x;
    int n4 = n_edges >> 2;
    const int4* j4 = (const int4*)job_idx;
    const int4* m4 = (const int4*)mach_idx;
    for (int e = i; e < n4; e += stride) {
        int4 a = __ldg(j4 + e);
        int4 b = __ldg(m4 + e);
        atomicAdd(&g_job_cur[a.x], 1);  atomicAdd(&g_job_cur[a.y], 1);
        atomicAdd(&g_job_cur[a.z], 1);  atomicAdd(&g_job_cur[a.w], 1);
        atomicAdd(&g_mach_cur[b.x], 1); atomicAdd(&g_mach_cur[b.y], 1);
        atomicAdd(&g_mach_cur[b.z], 1); atomicAdd(&g_mach_cur[b.w], 1);
    }
    int rem = n_edges & 3;
    if (i < rem) {
        int e = n4 * 4 + i;
        atomicAdd(&g_job_cur[__ldg(job_idx + e)], 1);
        atomicAdd(&g_mach_cur[__ldg(mach_idx + e)], 1);
    }
}

// Pass A: per-block (512 elems) local exclusive scan into off[], block total -> g_bsum.
__global__ void scanA_kernel() {
    bool is_mach = blockIdx.x >= JB;
    const int* cnt = is_mach ? g_mach_cur : g_job_cur;
    int* off = is_mach ? g_mach_off : g_job_off;
    int n    = is_mach ? N_MACH : N_JOBS;
    int b    = is_mach ? (blockIdx.x - JB) : blockIdx.x;

    int tid = threadIdx.x;            // 256 threads, 2 elems each
    int lane = tid & 31, wid = tid >> 5;
    int idx = b * SCAN_CHUNK + tid * 2;
    int v0 = (idx     < n) ? cnt[idx]     : 0;
    int v1 = (idx + 1 < n) ? cnt[idx + 1] : 0;
    int tsum = v0 + v1;
    int incl = tsum;
    #pragma unroll
    for (int o = 1; o < 32; o <<= 1) {
        int t = __shfl_up_sync(0xffffffffu, incl, o);
        if (lane >= o) incl += t;
    }
    __shared__ int wsum[8];
    if (lane == 31) wsum[wid] = incl;
    __syncthreads();
    if (tid < 8) {
        int ws = wsum[tid];
        #pragma unroll
        for (int o = 1; o < 8; o <<= 1) {
            int t = __shfl_up_sync(0xffu, ws, o);
            if (tid >= o) ws += t;
        }
        wsum[tid] = ws;
    }
    __syncthreads();
    int base = (wid == 0 ? 0 : wsum[wid - 1]) + (incl - tsum);
    if (idx     < n) off[idx]     = base;
    if (idx + 1 < n) off[idx + 1] = base + v0;
    if (tid == 255) g_bsum[blockIdx.x] = wsum[7];
}

// Pass B: one block exclusive-scans g_bsum for jobs [0,JB) and machines [JB,JB+MB).
__global__ void scanB_kernel(int n_edges) {
    int tid = threadIdx.x;   // 256 >= max(JB, MB)
    int lane = tid & 31, wid = tid >> 5;
    __shared__ int wsum[8];
    #pragma unroll
    for (int seg = 0; seg < 2; seg++) {
        int n = seg ? MB : JB;
        int o0 = seg ? JB : 0;
        int v = (tid < n) ? g_bsum[o0 + tid] : 0;
        int incl = v;
        #pragma unroll
        for (int o = 1; o < 32; o <<= 1) {
            int t = __shfl_up_sync(0xffffffffu, incl, o);
            if (lane >= o) incl += t;
        }
        if (lane == 31) wsum[wid] = incl;
        __syncthreads();
        if (tid < 8) {
            int ws = wsum[tid];
            #pragma unroll
            for (int o = 1; o < 8; o <<= 1) {
                int t = __shfl_up_sync(0xffu, ws, o);
                if (tid >= o) ws += t;
            }
            wsum[tid] = ws;
        }
        __syncthreads();
        int excl = (wid == 0 ? 0 : wsum[wid - 1]) + (incl - v);
        if (tid < n) g_bsum[o0 + tid] = excl;
        __syncthreads();
    }
    if (tid == 0) { g_job_off[N_JOBS] = n_edges; g_mach_off[N_MACH] = n_edges; }
}

// Pass C: add block bases, copy off -> cur (fill cursors).
__global__ void scanC_kernel() {
    bool is_mach = blockIdx.x >= JB;
    int* off = is_mach ? g_mach_off : g_job_off;
    int* cur = is_mach ? g_mach_cur : g_job_cur;
    int n    = is_mach ? N_MACH : N_JOBS;
    int b    = is_mach ? (blockIdx.x - JB) : blockIdx.x;
    int base = g_bsum[blockIdx.x];
    int idx = b * SCAN_CHUNK + threadIdx.x * 2;
    if (idx < n)     { int v = off[idx]     + base; off[idx]     = v; cur[idx]     = v; }
    if (idx + 1 < n) { int v = off[idx + 1] + base; off[idx + 1] = v; cur[idx + 1] = v; }
}

// 4 edges per iteration -> 8 independent atomic+store chains.
__global__ void fill_kernel(const int* __restrict__ job_idx,
                            const int* __restrict__ mach_idx, int n_edges) {
    int i = blockIdx.x * blockDim.x + threadIdx.x;
    int stride = gridDim.x * blockDim.x;
    int n4 = n_edges >> 2;
    const int4* j4 = (const int4*)job_idx;
    const int4* m4 = (const int4*)mach_idx;
    for (int e = i; e < n4; e += stride) {
        int4 a = __ldg(j4 + e);
        int4 b = __ldg(m4 + e);
        int p0 = atomicAdd(&g_job_cur[a.x], 1);
        int p1 = atomicAdd(&g_job_cur[a.y], 1);
        int p2 = atomicAdd(&g_job_cur[a.z], 1);
        int p3 = atomicAdd(&g_job_cur[a.w], 1);
        int q0 = atomicAdd(&g_mach_cur[b.x], 1);
        int q1 = atomicAdd(&g_mach_cur[b.y], 1);
        int q2 = atomicAdd(&g_mach_cur[b.z], 1);
        int q3 = atomicAdd(&g_mach_cur[b.w], 1);
        g_job_nbr[p0] = b.x;  g_job_nbr[p1] = b.y;
        g_job_nbr[p2] = b.z;  g_job_nbr[p3] = b.w;
        g_mach_nbr[q0] = a.x; g_mach_nbr[q1] = a.y;
        g_mach_nbr[q2] = a.z; g_mach_nbr[q3] = a.w;
    }
    int rem = n_edges & 3;
    if (i < rem) {
        int e = n4 * 4 + i;
        int j = __ldg(job_idx + e);
        int m = __ldg(mach_idx + e);
        g_job_nbr[atomicAdd(&g_job_cur[j], 1)] = m;
        g_mach_nbr[atomicAdd(&g_mach_cur[m], 1)] = j;
    }
}

// Warp per row: CSR gather-mean for both sides. Lane owns 4 consecutive floats.
// High occupancy + unroll-2 -> L2-bandwidth bound (the LTS cap is the floor).
__global__ void agg_kernel(const float* __restrict__ job_h,
                           const float* __restrict__ machine_h) {
    int gw = (blockIdx.x * blockDim.x + threadIdx.x) >> 5;
    if (gw >= N_JOBS + N_MACH) return;
    int lane = threadIdx.x & 31;
    const int* off; const int* nbr; const float* src; float* dst; int r;
    if (gw < N_JOBS) { r = gw;          off = g_job_off;  nbr = g_job_nbr;  src = machine_h; dst = g_job_agg; }
    else             { r = gw - N_JOBS; off = g_mach_off; nbr = g_mach_nbr; src = job_h;     dst = g_mach_agg; }
    int s = off[r], e = off[r + 1];
    int c = lane << 2;
    float4 a = make_float4(0.f, 0.f, 0.f, 0.f);
    float4 b = a;
    int p = s;
    for (; p + 2 <= e; p += 2) {
        int n0 = __ldg(nbr + p);
        int n1 = __ldg(nbr + p + 1);
        float4 v0 = *(const float4*)(src + (size_t)n0 * DIM + c);
        float4 v1 = *(const float4*)(src + (size_t)n1 * DIM + c);
        a.x += v0.x; a.y += v0.y; a.z += v0.z; a.w += v0.w;
        b.x += v1.x; b.y += v1.y; b.z += v1.z; b.w += v1.w;
    }
    if (p < e) {
        int n0 = __ldg(nbr + p);
        float4 v0 = *(const float4*)(src + (size_t)n0 * DIM + c);
        a.x += v0.x; a.y += v0.y; a.z += v0.z; a.w += v0.w;
    }
    float idg = 1.0f / (float)max(e - s, 1);
    a.x = (a.x + b.x) * idg;
    a.y = (a.y + b.y) * idg;
    a.z = (a.z + b.z) * idg;
    a.w = (a.w + b.w) * idg;
    *(float4*)(dst + (size_t)r * DIM + c) = a;
}

// Persistent GEMM+ReLU+LN. 148 blocks x 512 threads. W loaded into smem ONCE
// per SM (conflict-free STS: lane->o so bank=o%32 distinct), then tiles of 64
// rows with NO syncthreads in the loop. X read via uniform-broadcast LDG (each
// row read exactly once chip-wide). Inner product: packed fma.rn.f32x2.
// Warp tr owns rows tr*4..tr*4+3; lane tc owns cols tc*4..tc*4+3; LN via shfl.
__global__ __launch_bounds__(512, 1) void gemm_ln_kernel(
    const float* __restrict__ h,
    const float* __restrict__ W,      // [128][256] row-major
    const float* __restrict__ bias,
    const float* __restrict__ ln_s,
    const float* __restrict__ ln_b,
    float* __restrict__ out,
    int n_rows, int mode)
{
    const float* agg = mode ? g_mach_agg : g_job_agg;
    extern __shared__ float Wt[];     // [256][128]: Wt[k*128+o]
    int tid = threadIdx.x;

    // W -> smem transposed. lane->o mapping: STS banks (o mod 32) all distinct.
    #pragma unroll 4
    for (int it = 0; it < 16; it++) {
        int idx4 = tid + it * 512;         // 8192 float4 total
        int o  = idx4 & 127;
        int k4 = (idx4 >> 7) << 2;
        float4 w = *(const float4*)(W + o * KDIM + k4);
        Wt[(k4 + 0) * DIM + o] = w.x;
        Wt[(k4 + 1) * DIM + o] = w.y;
        Wt[(k4 + 2) * DIM + o] = w.z;
        Wt[(k4 + 3) * DIM + o] = w.w;
    }
    __syncthreads();

    int tc = tid & 31;
    int tr = tid >> 5;
    float4 bb = *(const float4*)(bias + tc * 4);
    float4 gs = *(const float4*)(ln_s + tc * 4);
    float4 gb = *(const float4*)(ln_b + tc * 4);

    int ntiles = (n_rows + BM - 1) / BM;
    for (int tile = blockIdx.x; tile < ntiles; tile += gridDim.x) {
        int rbase = tile * BM + tr * 4;
        // Clamped row pointers (rows past n_rows compute garbage, never stored)
        const float* xp[4];
        const float* ap[4];
        #pragma unroll
        for (int i = 0; i < 4; i++) {
            int rr = min(rbase + i, n_rows - 1);
            xp[i] = h   + (size_t)rr * DIM;
            ap[i] = agg + (size_t)rr * DIM;
        }

        unsigned long long acc[4][2];
        #pragma unroll
        for (int i = 0; i < 4; i++) { acc[i][0] = 0ull; acc[i][1] = 0ull; }

        #pragma unroll 1
        for (int half = 0; half < 2; half++) {
            const float* const* src = half ? ap : xp;
            const float* wh = Wt + (size_t)(half * 128) * DIM;
            #pragma unroll 2
            for (int k0 = 0; k0 < 128; k0 += 4) {
                const float* wp = wh + (size_t)k0 * DIM + tc * 4;
                ulonglong2 bq[4];
                #pragma unroll
                for (int kk = 0; kk < 4; kk++)
                    bq[kk] = *(const ulonglong2*)(wp + kk * DIM);
                #pragma unroll
                for (int i = 0; i < 4; i++) {
                    float4 a = *(const float4*)(src[i] + k0);
                    float av[4] = {a.x, a.y, a.z, a.w};
                    #pragma unroll
                    for (int kk = 0; kk < 4; kk++) {
                        unsigned long long aa;
                        asm("mov.b64 %0, {%1, %1};" : "=l"(aa) : "f"(av[kk]));
                        asm("fma.rn.f32x2 %0, %1, %2, %0;" : "+l"(acc[i][0]) : "l"(aa), "l"(bq[kk].x));
                        asm("fma.rn.f32x2 %0, %1, %2, %0;" : "+l"(acc[i][1]) : "l"(aa), "l"(bq[kk].y));
                    }
                }
            }
        }

        // Epilogue: +bias, relu, LayerNorm per row, store.
        #pragma unroll
        for (int i = 0; i < 4; i++) {
            int grow = rbase + i;
            float v0, v1, v2, v3;
            asm("mov.b64 {%0, %1}, %2;" : "=f"(v0), "=f"(v1) : "l"(acc[i][0]));
            asm("mov.b64 {%0, %1}, %2;" : "=f"(v2), "=f"(v3) : "l"(acc[i][1]));
            v0 = fmaxf(v0 + bb.x, 0.f);
            v1 = fmaxf(v1 + bb.y, 0.f);
            v2 = fmaxf(v2 + bb.z, 0.f);
            v3 = fmaxf(v3 + bb.w, 0.f);
            float sum = v0 + v1 + v2 + v3;
            float sq  = v0*v0 + v1*v1 + v2*v2 + v3*v3;
            #pragma unroll
            for (int o = 16; o > 0; o >>= 1) {
                sum += __shfl_xor_sync(0xffffffffu, sum, o);
                sq  += __shfl_xor_sync(0xffffffffu, sq,  o);
            }
            float mean = sum * (1.0f / 128.0f);
            float var  = sq * (1.0f / 128.0f) - mean * mean;
            float rstd = rsqrtf(var + LN_EPS);
            if (grow < n_rows) {
                float4 o4;
                o4.x = (v0 - mean) * rstd * gs.x + gb.x;
                o4.y = (v1 - mean) * rstd * gs.y + gb.y;
                o4.z = (v2 - mean) * rstd * gs.z + gb.z;
                o4.w = (v3 - mean) * rstd * gs.w + gb.w;
                *(float4*)(out + (size_t)grow * DIM + tc * 4) = o4;
            }
        }
    }
}

extern "C" void kernel_launch(void* const* d_in, const int* in_sizes, int n_in,
                              void* d_out, int out_size)
{
    const float* job_h     = (const float*)d_in[0];
    const float* machine_h = (const float*)d_in[1];
    const float* W_job_w   = (const float*)d_in[2];
    const float* W_job_b   = (const float*)d_in[3];
    const float* W_mach_w  = (const float*)d_in[4];
    const float* W_mach_b  = (const float*)d_in[5];
    const float* lnj_s     = (const float*)d_in[6];
    const float* lnj_b     = (const float*)d_in[7];
    const float* lnm_s     = (const float*)d_in[8];
    const float* lnm_b     = (const float*)d_in[9];
    const int*   job_idx   = (const int*)d_in[10];
    const int*   mach_idx  = (const int*)d_in[11];
    float* out = (float*)d_out;
    int n_edges = in_sizes[10];

    const int smem_bytes = KDIM * DIM * (int)sizeof(float);  // 131072
    cudaFuncSetAttribute(gemm_ln_kernel, cudaFuncAttributeMaxDynamicSharedMemorySize, smem_bytes);

    zero_cnt_kernel<<<128, 256>>>();
    hist_kernel<<<592, 256>>>(job_idx, mach_idx, n_edges);
    scanA_kernel<<<JB + MB, 256>>>();
    scanB_kernel<<<1, 256>>>(n_edges);
    scanC_kernel<<<JB + MB, 256>>>();
    fill_kernel<<<592, 256>>>(job_idx, mach_idx, n_edges);

    // warp per row: (110000 rows * 32 lanes) / 256 threads
    agg_kernel<<<(int)(((size_t)(N_JOBS + N_MACH) * 32 + 255) / 256), 256>>>(job_h, machine_h);

    gemm_ln_kernel<<<148, 512, smem_bytes>>>(
        job_h, W_job_w, W_job_b, lnj_s, lnj_b, out, N_JOBS, 0);
    gemm_ln_kernel<<<148, 512, smem_bytes>>>(
        machine_h, W_mach_w, W_mach_b, lnm_s, lnm_b,
        out + (size_t)N_JOBS * DIM, N_MACH, 1);
}

// round 7
// speedup vs baseline: 1.6732x; 1.1194x over previous
#include <cuda_runtime.h>
#include <cstdint>
#include <cstddef>

#define N_JOBS 100000
#define N_MACH 10000
#define DIM 128
#define KDIM 256
#define BM 64
#define LN_EPS 1e-5f
#define MAX_EDGES 1600000

#define JOB_TILES ((N_JOBS + BM - 1) / BM)    // 1563
#define MACH_TILES ((N_MACH + BM - 1) / BM)   // 157

#define SCAN_CHUNK 512
#define JB ((N_JOBS + SCAN_CHUNK - 1) / SCAN_CHUNK)   // 196
#define MB ((N_MACH + SCAN_CHUNK - 1) / SCAN_CHUNK)   // 20

// Scratch device globals (no allocations allowed): CSR (~14MB) + agg (~56MB).
__device__ int g_job_off[N_JOBS + 1];
__device__ int g_mach_off[N_MACH + 1];
__device__ int g_job_cur[N_JOBS];
__device__ int g_mach_cur[N_MACH];
__device__ int g_job_nbr[MAX_EDGES];
__device__ int g_mach_nbr[MAX_EDGES];
__device__ int g_bsum[JB + MB];
__device__ __align__(256) float g_job_agg[(size_t)N_JOBS * DIM];
__device__ __align__(256) float g_mach_agg[(size_t)N_MACH * DIM];

__global__ void zero_cnt_kernel() {
    int i = blockIdx.x * blockDim.x + threadIdx.x;
    int stride = gridDim.x * blockDim.x;
    for (int t = i; t < N_JOBS; t += stride) g_job_cur[t] = 0;
    for (int t = i; t < N_MACH; t += stride) g_mach_cur[t] = 0;
}

// 4 edges per iteration -> 8 independent atomics in flight.
__global__ void hist_kernel(const int* __restrict__ job_idx,
                            const int* __restrict__ mach_idx, int n_edges) {
    int i = blockIdx.x * blockDim.x + threadIdx.x;
    int stride = gridDim.x * blockDim.x;
    int n4 = n_edges >> 2;
    const int4* j4 = (const int4*)job_idx;
    const int4* m4 = (const int4*)mach_idx;
    for (int e = i; e < n4; e += stride) {
        int4 a = __ldg(j4 + e);
        int4 b = __ldg(m4 + e);
        atomicAdd(&g_job_cur[a.x], 1);  atomicAdd(&g_job_cur[a.y], 1);
        atomicAdd(&g_job_cur[a.z], 1);  atomicAdd(&g_job_cur[a.w], 1);
        atomicAdd(&g_mach_cur[b.x], 1); atomicAdd(&g_mach_cur[b.y], 1);
        atomicAdd(&g_mach_cur[b.z], 1); atomicAdd(&g_mach_cur[b.w], 1);
    }
    int rem = n_edges & 3;
    if (i < rem) {
        int e = n4 * 4 + i;
        atomicAdd(&g_job_cur[__ldg(job_idx + e)], 1);
        atomicAdd(&g_mach_cur[__ldg(mach_idx + e)], 1);
    }
}

// Pass A: per-block (512 elems) local exclusive scan into off[], block total -> g_bsum.
__global__ void scanA_kernel() {
    bool is_mach = blockIdx.x >= JB;
    const int* cnt = is_mach ? g_mach_cur : g_job_cur;
    int* off = is_mach ? g_mach_off : g_job_off;
    int n    = is_mach ? N_MACH : N_JOBS;
    int b    = is_mach ? (blockIdx.x - JB) : blockIdx.x;

    int tid = threadIdx.x;            // 256 threads, 2 elems each
    int lane = tid & 31, wid = tid >> 5;
    int idx = b * SCAN_CHUNK + tid * 2;
    int v0 = (idx     < n) ? cnt[idx]     : 0;
    int v1 = (idx + 1 < n) ? cnt[idx + 1] : 0;
    int tsum = v0 + v1;
    int incl = tsum;
    #pragma unroll
    for (int o = 1; o < 32; o <<= 1) {
        int t = __shfl_up_sync(0xffffffffu, incl, o);
        if (lane >= o) incl += t;
    }
    __shared__ int wsum[8];
    if (lane == 31) wsum[wid] = incl;
    __syncthreads();
    if (tid < 8) {
        int ws = wsum[tid];
        #pragma unroll
        for (int o = 1; o < 8; o <<= 1) {
            int t = __shfl_up_sync(0xffu, ws, o);
            if (tid >= o) ws += t;
        }
        wsum[tid] = ws;
    }
    __syncthreads();
    int base = (wid == 0 ? 0 : wsum[wid - 1]) + (incl - tsum);
    if (idx     < n) off[idx]     = base;
    if (idx + 1 < n) off[idx + 1] = base + v0;
    if (tid == 255) g_bsum[blockIdx.x] = wsum[7];
}

// Pass B: one block exclusive-scans g_bsum for jobs [0,JB) and machines [JB,JB+MB).
__global__ void scanB_kernel(int n_edges) {
    int tid = threadIdx.x;   // 256 >= max(JB, MB)
    int lane = tid & 31, wid = tid >> 5;
    __shared__ int wsum[8];
    #pragma unroll
    for (int seg = 0; seg < 2; seg++) {
        int n = seg ? MB : JB;
        int o0 = seg ? JB : 0;
        int v = (tid < n) ? g_bsum[o0 + tid] : 0;
        int incl = v;
        #pragma unroll
        for (int o = 1; o < 32; o <<= 1) {
            int t = __shfl_up_sync(0xffffffffu, incl, o);
            if (lane >= o) incl += t;
        }
        if (lane == 31) wsum[wid] = incl;
        __syncthreads();
        if (tid < 8) {
            int ws = wsum[tid];
            #pragma unroll
            for (int o = 1; o < 8; o <<= 1) {
                int t = __shfl_up_sync(0xffu, ws, o);
                if (tid >= o) ws += t;
            }
            wsum[tid] = ws;
        }
        __syncthreads();
        int excl = (wid == 0 ? 0 : wsum[wid - 1]) + (incl - v);
        if (tid < n) g_bsum[o0 + tid] = excl;
        __syncthreads();
    }
    if (tid == 0) { g_job_off[N_JOBS] = n_edges; g_mach_off[N_MACH] = n_edges; }
}

// Pass C: add block bases, copy off -> cur (fill cursors).
__global__ void scanC_kernel() {
    bool is_mach = blockIdx.x >= JB;
    int* off = is_mach ? g_mach_off : g_job_off;
    int* cur = is_mach ? g_mach_cur : g_job_cur;
    int n    = is_mach ? N_MACH : N_JOBS;
    int b    = is_mach ? (blockIdx.x - JB) : blockIdx.x;
    int base = g_bsum[blockIdx.x];
    int idx = b * SCAN_CHUNK + threadIdx.x * 2;
    if (idx < n)     { int v = off[idx]     + base; off[idx]     = v; cur[idx]     = v; }
    if (idx + 1 < n) { int v = off[idx + 1] + base; off[idx + 1] = v; cur[idx + 1] = v; }
}

// 4 edges per iteration -> 8 independent atomic+store chains.
__global__ void fill_kernel(const int* __restrict__ job_idx,
                            const int* __restrict__ mach_idx, int n_edges) {
    int i = blockIdx.x * blockDim.x + threadIdx.x;
    int stride = gridDim.x * blockDim.x;
    int n4 = n_edges >> 2;
    const int4* j4 = (const int4*)job_idx;
    const int4* m4 = (const int4*)mach_idx;
    for (int e = i; e < n4; e += stride) {
        int4 a = __ldg(j4 + e);
        int4 b = __ldg(m4 + e);
        int p0 = atomicAdd(&g_job_cur[a.x], 1);
        int p1 = atomicAdd(&g_job_cur[a.y], 1);
        int p2 = atomicAdd(&g_job_cur[a.z], 1);
        int p3 = atomicAdd(&g_job_cur[a.w], 1);
        int q0 = atomicAdd(&g_mach_cur[b.x], 1);
        int q1 = atomicAdd(&g_mach_cur[b.y], 1);
        int q2 = atomicAdd(&g_mach_cur[b.z], 1);
        int q3 = atomicAdd(&g_mach_cur[b.w], 1);
        g_job_nbr[p0] = b.x;  g_job_nbr[p1] = b.y;
        g_job_nbr[p2] = b.z;  g_job_nbr[p3] = b.w;
        g_mach_nbr[q0] = a.x; g_mach_nbr[q1] = a.y;
        g_mach_nbr[q2] = a.z; g_mach_nbr[q3] = a.w;
    }
    int rem = n_edges & 3;
    if (i < rem) {
        int e = n4 * 4 + i;
        int j = __ldg(job_idx + e);
        int m = __ldg(mach_idx + e);
        g_job_nbr[atomicAdd(&g_job_cur[j], 1)] = m;
        g_mach_nbr[atomicAdd(&g_mach_cur[m], 1)] = j;
    }
}

// Warp per row: CSR gather-mean, both sides. Lane owns 4 consecutive floats.
// Unroll-4: 4 independent 512B gathers in flight per warp -> LTS-cap bound.
__global__ __launch_bounds__(256) void agg_kernel(const float* __restrict__ job_h,
                                                  const float* __restrict__ machine_h) {
    int gw = (blockIdx.x * blockDim.x + threadIdx.x) >> 5;
    if (gw >= N_JOBS + N_MACH) return;
    int lane = threadIdx.x & 31;
    const int* off; const int* nbr; const float* src; float* dst; int r;
    if (gw < N_JOBS) { r = gw;          off = g_job_off;  nbr = g_job_nbr;  src = machine_h; dst = g_job_agg; }
    else             { r = gw - N_JOBS; off = g_mach_off; nbr = g_mach_nbr; src = job_h;     dst = g_mach_agg; }
    int s = off[r], e = off[r + 1];
    int c = lane << 2;
    float4 a0 = make_float4(0.f, 0.f, 0.f, 0.f);
    float4 a1 = a0, a2 = a0, a3 = a0;
    int p = s;
    for (; p + 4 <= e; p += 4) {
        int n0 = __ldg(nbr + p);
        int n1 = __ldg(nbr + p + 1);
        int n2 = __ldg(nbr + p + 2);
        int n3 = __ldg(nbr + p + 3);
        float4 v0 = *(const float4*)(src + (size_t)n0 * DIM + c);
        float4 v1 = *(const float4*)(src + (size_t)n1 * DIM + c);
        float4 v2 = *(const float4*)(src + (size_t)n2 * DIM + c);
        float4 v3 = *(const float4*)(src + (size_t)n3 * DIM + c);
        a0.x += v0.x; a0.y += v0.y; a0.z += v0.z; a0.w += v0.w;
        a1.x += v1.x; a1.y += v1.y; a1.z += v1.z; a1.w += v1.w;
        a2.x += v2.x; a2.y += v2.y; a2.z += v2.z; a2.w += v2.w;
        a3.x += v3.x; a3.y += v3.y; a3.z += v3.z; a3.w += v3.w;
    }
    for (; p < e; p++) {
        int n0 = __ldg(nbr + p);
        float4 v0 = *(const float4*)(src + (size_t)n0 * DIM + c);
        a0.x += v0.x; a0.y += v0.y; a0.z += v0.z; a0.w += v0.w;
    }
    float idg = 1.0f / (float)max(e - s, 1);
    a0.x = (a0.x + a1.x + a2.x + a3.x) * idg;
    a0.y = (a0.y + a1.y + a2.y + a3.y) * idg;
    a0.z = (a0.z + a1.z + a2.z + a3.z) * idg;
    a0.w = (a0.w + a1.w + a2.w + a3.w) * idg;
    *(float4*)(dst + (size_t)r * DIM + c) = a0;
}

// ---- merged persistent GEMM+ReLU+LN -----------------------------------------
// 148 blocks x 256 threads, smem = Wt[256][128] (128KB) + Xs[64][256] (64KB).
// Per tile: stage X (coalesced LDG -> smem), sync, compute (warp w owns rows
// w*8..w*8+7; lane tc owns cols 4tc..4tc+3; f32x2 FMAs; all smem reads either
// 4-phase-minimal or broadcast), LN via shfl, sync. Job phase then mach phase
// (Wt reloaded once at the boundary).

__device__ __forceinline__ void load_W_smem(float* Wt, const float* __restrict__ W, int tid) {
    #pragma unroll 4
    for (int it = 0; it < 32; it++) {
        int idx4 = tid + it * 256;          // 8192 float4 of W
        int o  = idx4 & 127;
        int k4 = (idx4 >> 7) << 2;
        float4 w = *(const float4*)(W + o * KDIM + k4);
        Wt[(k4 + 0) * DIM + o] = w.x;
        Wt[(k4 + 1) * DIM + o] = w.y;
        Wt[(k4 + 2) * DIM + o] = w.z;
        Wt[(k4 + 3) * DIM + o] = w.w;
    }
}

__device__ __forceinline__ void do_tile(
    int tile, const float* __restrict__ h, const float* __restrict__ agg,
    float4 bb, float4 gs, float4 gb,
    float* __restrict__ out, int n_rows,
    const float* Wt, float* Xs, int tid)
{
    int row0 = tile * BM;
    // Stage X tile: 4096 float4, 16 per thread, coalesced.
    #pragma unroll 4
    for (int it = 0; it < 16; it++) {
        int idx4 = tid + it * 256;
        int r  = idx4 >> 6;
        int c4 = (idx4 & 63) << 2;
        int grow = min(row0 + r, n_rows - 1);
        float4 v;
        if (c4 < DIM) v = *(const float4*)(h + (size_t)grow * DIM + c4);
        else          v = *(const float4*)(agg + (size_t)grow * DIM + (c4 - DIM));
        *(float4*)(Xs + r * KDIM + c4) = v;
    }
    __syncthreads();

    int tc = tid & 31;
    int w  = tid >> 5;
    unsigned long long acc[8][2];
    #pragma unroll
    for (int i = 0; i < 8; i++) { acc[i][0] = 0ull; acc[i][1] = 0ull; }
    const float* xbase = Xs + (size_t)(w * 8) * KDIM;

    #pragma unroll 2
    for (int k0 = 0; k0 < KDIM; k0 += 4) {
        const float* wp = Wt + (size_t)k0 * DIM + tc * 4;
        ulonglong2 bq[4];
        #pragma unroll
        for (int kk = 0; kk < 4; kk++)
            bq[kk] = *(const ulonglong2*)(wp + kk * DIM);
        #pragma unroll
        for (int i = 0; i < 8; i++) {
            float4 a = *(const float4*)(xbase + i * KDIM + k0);
            float av[4] = {a.x, a.y, a.z, a.w};
            #pragma unroll
            for (int kk = 0; kk < 4; kk++) {
                unsigned long long aa;
                asm("mov.b64 %0, {%1, %1};" : "=l"(aa) : "f"(av[kk]));
                asm("fma.rn.f32x2 %0, %1, %2, %0;" : "+l"(acc[i][0]) : "l"(aa), "l"(bq[kk].x));
                asm("fma.rn.f32x2 %0, %1, %2, %0;" : "+l"(acc[i][1]) : "l"(aa), "l"(bq[kk].y));
            }
        }
    }

    // Epilogue: +bias, relu, LayerNorm per row (row in one warp), store.
    #pragma unroll
    for (int i = 0; i < 8; i++) {
        int grow = row0 + w * 8 + i;
        float v0, v1, v2, v3;
        asm("mov.b64 {%0, %1}, %2;" : "=f"(v0), "=f"(v1) : "l"(acc[i][0]));
        asm("mov.b64 {%0, %1}, %2;" : "=f"(v2), "=f"(v3) : "l"(acc[i][1]));
        v0 = fmaxf(v0 + bb.x, 0.f);
        v1 = fmaxf(v1 + bb.y, 0.f);
        v2 = fmaxf(v2 + bb.z, 0.f);
        v3 = fmaxf(v3 + bb.w, 0.f);
        float sum = v0 + v1 + v2 + v3;
        float sq  = v0*v0 + v1*v1 + v2*v2 + v3*v3;
        #pragma unroll
        for (int o = 16; o > 0; o >>= 1) {
            sum += __shfl_xor_sync(0xffffffffu, sum, o);
            sq  += __shfl_xor_sync(0xffffffffu, sq,  o);
        }
        float mean = sum * (1.0f / 128.0f);
        float var  = sq * (1.0f / 128.0f) - mean * mean;
        float rstd = rsqrtf(var + LN_EPS);
        if (grow < n_rows) {
            float4 o4;
            o4.x = (v0 - mean) * rstd * gs.x + gb.x;
            o4.y = (v1 - mean) * rstd * gs.y + gb.y;
            o4.z = (v2 - mean) * rstd * gs.z + gb.z;
            o4.w = (v3 - mean) * rstd * gs.w + gb.w;
            *(float4*)(out + (size_t)grow * DIM + tc * 4) = o4;
        }
    }
    __syncthreads();   // Xs reused next tile
}

__global__ __launch_bounds__(256, 1) void gemm_ln_kernel(
    const float* __restrict__ job_h, const float* __restrict__ machine_h,
    const float* __restrict__ Wj, const float* __restrict__ bj,
    const float* __restrict__ lnsj, const float* __restrict__ lnbj,
    const float* __restrict__ Wm, const float* __restrict__ bm,
    const float* __restrict__ lnsm, const float* __restrict__ lnbm,
    float* __restrict__ out)
{
    extern __shared__ float smem[];
    float* Wt = smem;                 // 256*128
    float* Xs = smem + KDIM * DIM;    // 64*256
    int tid = threadIdx.x;
    int tc = tid & 31;

    // ---- phase 0: jobs ----
    load_W_smem(Wt, Wj, tid);
    __syncthreads();
    {
        float4 bb = *(const float4*)(bj + tc * 4);
        float4 gs = *(const float4*)(lnsj + tc * 4);
        float4 gb = *(const float4*)(lnbj + tc * 4);
        int t = blockIdx.x;
        for (; t < JOB_TILES; t += gridDim.x)
            do_tile(t, job_h, g_job_agg, bb, gs, gb, out, N_JOBS, Wt, Xs, tid);
    }

    // ---- phase 1: machines ----
    __syncthreads();
    load_W_smem(Wt, Wm, tid);
    __syncthreads();
    {
        float4 bb = *(const float4*)(bm + tc * 4);
        float4 gs = *(const float4*)(lnsm + tc * 4);
        float4 gb = *(const float4*)(lnbm + tc * 4);
        // continue the stride: first mach tile for this block
        int t = blockIdx.x;
        while (t < JOB_TILES) t += gridDim.x;
        for (; t < JOB_TILES + MACH_TILES; t += gridDim.x)
            do_tile(t - JOB_TILES, machine_h, g_mach_agg, bb, gs, gb,
                    out + (size_t)N_JOBS * DIM, N_MACH, Wt, Xs, tid);
    }
}

extern "C" void kernel_launch(void* const* d_in, const int* in_sizes, int n_in,
                              void* d_out, int out_size)
{
    const float* job_h     = (const float*)d_in[0];
    const float* machine_h = (const float*)d_in[1];
    const float* W_job_w   = (const float*)d_in[2];
    const float* W_job_b   = (const float*)d_in[3];
    const float* W_mach_w  = (const float*)d_in[4];
    const float* W_mach_b  = (const float*)d_in[5];
    const float* lnj_s     = (const float*)d_in[6];
    const float* lnj_b     = (const float*)d_in[7];
    const float* lnm_s     = (const float*)d_in[8];
    const float* lnm_b     = (const float*)d_in[9];
    const int*   job_idx   = (const int*)d_in[10];
    const int*   mach_idx  = (const int*)d_in[11];
    float* out = (float*)d_out;
    int n_edges = in_sizes[10];

    const int smem_bytes = (KDIM * DIM + BM * KDIM) * (int)sizeof(float);  // 196608
    cudaFuncSetAttribute(gemm_ln_kernel, cudaFuncAttributeMaxDynamicSharedMemorySize, smem_bytes);

    zero_cnt_kernel<<<128, 256>>>();
    hist_kernel<<<592, 256>>>(job_idx, mach_idx, n_edges);
    scanA_kernel<<<JB + MB, 256>>>();
    scanB_kernel<<<1, 256>>>(n_edges);
    scanC_kernel<<<JB + MB, 256>>>();
    fill_kernel<<<592, 256>>>(job_idx, mach_idx, n_edges);

    agg_kernel<<<(int)(((size_t)(N_JOBS + N_MACH) * 32 + 255) / 256), 256>>>(job_h, machine_h);

    gemm_ln_kernel<<<148, 256, smem_bytes>>>(
        job_h, machine_h,
        W_job_w, W_job_b, lnj_s, lnj_b,
        W_mach_w, W_mach_b, lnm_s, lnm_b,
        out);
}